// round 1
// baseline (speedup 1.0000x reference)
#include <cuda_runtime.h>

// VQPatchEncoder: patchify -> (unnormalized) sim argmax vs codebook ->
// embedding means (global + agent) + VSA binding over central patches.
//
// Inputs (metadata order):
//   d_in[0] pixels        float32 [1024, 3, 64, 64]
//   d_in[1] codebook      float32 [4096, 192]   (rows unit-norm)
//   d_in[2] embeddings    float32 [4096, 2048]
//   d_in[3] codebook_vsa  float32 [4096, 2048]  (0/1)
//   d_in[4] position_roles float32 [64, 2048]   (0/1)
// Output: concat flatten of (z_real[1024,2048], z_vsa[1024,2048],
//         indices[1024,64] cast to f32, z_local[1024,2048]) = 6,356,992 f32.

#define BATCH 1024
#define NP    64
#define PD    192
#define KC    4096
#define ED    2048
#define VD    2048
#define MROWS (BATCH * NP)   // 65536 patches

#define TM 128   // patches per block tile
#define TN 128   // codes per tile
#define TKK 16   // k-chunk

// Scratch (allocation-free rule: __device__ globals)
__device__ float g_patches[(size_t)MROWS * PD];   // 48 MB
__device__ int   g_indices[MROWS];

// ---------------------------------------------------------------------------
// 1) Patchify: pixels (B,3,64,64) -> patches (B*64, 192), patch-major rows.
//    patches[b, r*8+c, ch*64+pr*8+pc] = pixels[b, ch, r*8+pr, c*8+pc]
// ---------------------------------------------------------------------------
__global__ void patchify_kernel(const float* __restrict__ pixels) {
    int idx = blockIdx.x * blockDim.x + threadIdx.x;
    if (idx >= MROWS * PD) return;
    int d = idx % PD;
    int p = (idx / PD) % NP;
    int b = idx / (PD * NP);
    int ch = d >> 6;          // d / 64
    int rem = d & 63;
    int pr = rem >> 3, pc = rem & 7;
    int r = p >> 3, c = p & 7;
    g_patches[idx] =
        pixels[(((size_t)b * 3 + ch) * 64 + (r * 8 + pr)) * 64 + (c * 8 + pc)];
}

// ---------------------------------------------------------------------------
// 2) fp32 GEMM + fused argmax.
//    Block: 128 patches x (all 4096 codes in 32 tiles of 128), 256 threads,
//    8x8 register micro-tile per thread. Exact fp32, sequential-k order.
//    Tie-break: lowest code index (jnp.argmax first-occurrence).
// ---------------------------------------------------------------------------
__global__ __launch_bounds__(256) void gemm_argmax_kernel(
    const float* __restrict__ codebook, float* __restrict__ outI)
{
    __shared__ float As[TKK][TM + 1];   // +1 pad: conflict-free transposed store
    __shared__ float Bs[TKK][TN + 1];
    __shared__ float rv[TM][16];
    __shared__ int   ri[TM][16];

    const int tid = threadIdx.x;
    const int tx = tid & 15;        // code strip   (8 codes)
    const int ty = tid >> 4;        // patch strip  (8 patches)
    const int m0 = blockIdx.x * TM;

    const int lk = tid & 15;        // loader: k within chunk
    const int lm = tid >> 4;        // loader: base row

    float bval[8];
    int   bidx[8];
#pragma unroll
    for (int i = 0; i < 8; i++) { bval[i] = -3.0e38f; bidx[i] = 0; }

    for (int cc = 0; cc < KC / TN; ++cc) {
        float acc[8][8];
#pragma unroll
        for (int i = 0; i < 8; i++)
#pragma unroll
            for (int j = 0; j < 8; j++) acc[i][j] = 0.0f;

        const int n0 = cc * TN;
        for (int kt = 0; kt < PD / TKK; ++kt) {
            const int k0 = kt * TKK;
            // Each thread loads 8 rows at fixed k into transposed smem tiles.
#pragma unroll
            for (int t = 0; t < 8; t++) {
                int m = lm + t * 16;
                As[lk][m] = g_patches[(size_t)(m0 + m) * PD + k0 + lk];
                Bs[lk][m] = codebook [(size_t)(n0 + m) * PD + k0 + lk];
            }
            __syncthreads();
#pragma unroll
            for (int kk = 0; kk < TKK; ++kk) {
                float a[8], bb[8];
#pragma unroll
                for (int i = 0; i < 8; i++) a[i]  = As[kk][ty * 8 + i];
#pragma unroll
                for (int j = 0; j < 8; j++) bb[j] = Bs[kk][tx * 8 + j];
#pragma unroll
                for (int i = 0; i < 8; i++)
#pragma unroll
                    for (int j = 0; j < 8; j++)
                        acc[i][j] = fmaf(a[i], bb[j], acc[i][j]);
            }
            __syncthreads();
        }
        // Fold this code tile into running per-thread best.
        // Within a thread, idx is strictly ascending over (cc, j), so a
        // strict '>' keeps the first (lowest-index) maximum automatically.
#pragma unroll
        for (int i = 0; i < 8; i++) {
#pragma unroll
            for (int j = 0; j < 8; j++) {
                int idx = n0 + tx * 8 + j;
                if (acc[i][j] > bval[i]) { bval[i] = acc[i][j]; bidx[i] = idx; }
            }
        }
    }

    // Cross-thread (16 code strips) argmax reduction per patch.
#pragma unroll
    for (int i = 0; i < 8; i++) {
        rv[ty * 8 + i][tx] = bval[i];
        ri[ty * 8 + i][tx] = bidx[i];
    }
    __syncthreads();
    if (tid < TM) {
        float bv = rv[tid][0];
        int   bi = ri[tid][0];
#pragma unroll
        for (int t = 1; t < 16; t++) {
            float v = rv[tid][t];
            int   ix = ri[tid][t];
            if (v > bv || (v == bv && ix < bi)) { bv = v; bi = ix; }
        }
        g_indices[m0 + tid] = bi;
        outI[m0 + tid] = (float)bi;   // indices region of output
    }
}

// ---------------------------------------------------------------------------
// 3) z_real = mean over 64 patches of embeddings[idx]; z_local = mean over
//    the 9 AGENT patches (r,c in [3,6)). One block per image.
// ---------------------------------------------------------------------------
__global__ __launch_bounds__(256) void embed_mean_kernel(
    const float* __restrict__ emb,
    float* __restrict__ outR, float* __restrict__ outL)
{
    const int b = blockIdx.x;
    __shared__ int sIdx[NP];
    if (threadIdx.x < NP) sIdx[threadIdx.x] = g_indices[b * NP + threadIdx.x];
    __syncthreads();

    for (int e = threadIdx.x; e < ED; e += 256) {
        float s = 0.0f, sl = 0.0f;
#pragma unroll 8
        for (int p = 0; p < NP; p++) {
            float v = emb[(size_t)sIdx[p] * ED + e];
            s += v;
            int r = p >> 3, c = p & 7;
            if (r >= 3 && r < 6 && c >= 3 && c < 6) sl += v;
        }
        outR[(size_t)b * ED + e] = s * (1.0f / 64.0f);
        outL[(size_t)b * ED + e] = sl * (1.0f / 9.0f);
    }
}

// ---------------------------------------------------------------------------
// 4) VSA: for the 16 CENTRAL patches (r,c in [2,6)),
//    bound = (codebook_vsa[idx] + position_roles[patch]) mod 2  == XOR,
//    z_vsa = (sum over 16 > 8). One block per image.
// ---------------------------------------------------------------------------
__global__ __launch_bounds__(256) void vsa_kernel(
    const float* __restrict__ cbv, const float* __restrict__ roles,
    float* __restrict__ outV)
{
    const int b = blockIdx.x;
    __shared__ int sIdx[16];
    __shared__ int sPos[16];
    if (threadIdx.x < 16) {
        int r = 2 + (threadIdx.x >> 2);
        int c = 2 + (threadIdx.x & 3);
        int p = r * 8 + c;
        sPos[threadIdx.x] = p;
        sIdx[threadIdx.x] = g_indices[b * NP + p];
    }
    __syncthreads();

    for (int v = threadIdx.x; v < VD; v += 256) {
        int cnt = 0;
#pragma unroll
        for (int t = 0; t < 16; t++) {
            float a = cbv  [(size_t)sIdx[t] * VD + v];
            float q = roles[(size_t)sPos[t] * VD + v];
            cnt += (a != q);   // 0/1 floats: (a+q) mod 2 == (a != q)
        }
        outV[(size_t)b * VD + v] = (cnt > 8) ? 1.0f : 0.0f;
    }
}

// ---------------------------------------------------------------------------
extern "C" void kernel_launch(void* const* d_in, const int* in_sizes, int n_in,
                              void* d_out, int out_size)
{
    const float* pixels     = (const float*)d_in[0];
    const float* codebook   = (const float*)d_in[1];
    const float* embeddings = (const float*)d_in[2];
    const float* cbv        = (const float*)d_in[3];
    const float* roles      = (const float*)d_in[4];

    float* out  = (float*)d_out;
    float* outR = out;                                         // z_real
    float* outV = out + (size_t)BATCH * ED;                    // z_vsa
    float* outI = out + 2 * (size_t)BATCH * ED;                // indices
    float* outL = out + 2 * (size_t)BATCH * ED + (size_t)BATCH * NP; // z_local

    patchify_kernel<<<(MROWS * PD + 255) / 256, 256>>>(pixels);
    gemm_argmax_kernel<<<MROWS / TM, 256>>>(codebook, outI);
    embed_mean_kernel<<<BATCH, 256>>>(embeddings, outR, outL);
    vsa_kernel<<<BATCH, 256>>>(cbv, roles, outV);
}

// round 3
// speedup vs baseline: 2.1808x; 2.1808x over previous
#include <cuda_runtime.h>
#include <cuda_fp16.h>
#include <cstdint>

// ===========================================================================
// VQPatchEncoder — fp16-split mma.sync GEMM (sm_100 baseline ISA) +
// exact-argmax rescore path.
//
// sim = patches @ codebook^T computed as AhBh + AhBl + AlBh with fp16
// hi/lo split (abs err ~1e-5); rows with top2 gap < DELTA are rescored in
// exact fp32 (sequential-k), reproducing the reference argmax bit-exactly.
// ===========================================================================

#define BATCH 1024
#define NP    64
#define PD    192
#define KC    4096
#define ED    2048
#define VD    2048
#define MROWS (BATCH * NP)      // 65536
#define KP    576                // split-K: [Ah|Ah|Al] x [Bh;Bl;Bh]
#define BM    128
#define BN    128
#define KCH   64                 // k per chunk
#define NCHUNK (KP / KCH)        // 9
#define NTILE  (KC / BN)         // 32
#define TOTIT  (NTILE * NCHUNK)  // 288
#define AROWB  (KP * 2)          // 1152 bytes per A smem row
#define ASMEM  (BM * AROWB)      // 147456
#define BBUF   (KCH * BN * 2)    // 16384 per buffer
#define GEMM_SMEM (ASMEM + 2 * BBUF)   // 180224
#define DELTA 2e-4f

// ---- device-global scratch (no allocations allowed) -----------------------
__device__ __half g_a [(size_t)MROWS * KP];     // A' rows (75 MB)
__device__ __half g_bT[(size_t)KP * KC];        // B'^T [k][n] (4.7 MB)
__device__ float  g_patches[(size_t)MROWS * PD];
__device__ int    g_indices[MROWS];
__device__ int    g_flagged[MROWS];
__device__ int    g_nflag;

__device__ __forceinline__ uint32_t smem_u32(const void* p) {
    uint32_t a;
    asm("{ .reg .u64 t; cvta.to.shared.u64 t, %1; cvt.u32.u64 %0, t; }"
        : "=r"(a) : "l"(p));
    return a;
}
__device__ __forceinline__ void cp16(uint32_t dst, const void* src) {
    asm volatile("cp.async.cg.shared.global [%0], [%1], 16;"
                 :: "r"(dst), "l"(src) : "memory");
}
#define CP_COMMIT() asm volatile("cp.async.commit_group;" ::: "memory")
#define CP_WAIT(n)  asm volatile("cp.async.wait_group %0;" :: "n"(n) : "memory")

__device__ __forceinline__ void ldsm4(uint32_t* r, uint32_t addr) {
    asm volatile("ldmatrix.sync.aligned.m8n8.x4.shared.b16 {%0,%1,%2,%3}, [%4];"
                 : "=r"(r[0]), "=r"(r[1]), "=r"(r[2]), "=r"(r[3]) : "r"(addr));
}
__device__ __forceinline__ void ldsm4t(uint32_t* r, uint32_t addr) {
    asm volatile("ldmatrix.sync.aligned.m8n8.x4.trans.shared.b16 {%0,%1,%2,%3}, [%4];"
                 : "=r"(r[0]), "=r"(r[1]), "=r"(r[2]), "=r"(r[3]) : "r"(addr));
}
__device__ __forceinline__ void mma16816(float* c, const uint32_t* a,
                                         uint32_t b0, uint32_t b1) {
    asm volatile(
        "mma.sync.aligned.m16n8k16.row.col.f32.f16.f16.f32 "
        "{%0,%1,%2,%3}, {%4,%5,%6,%7}, {%8,%9}, {%0,%1,%2,%3};"
        : "+f"(c[0]), "+f"(c[1]), "+f"(c[2]), "+f"(c[3])
        : "r"(a[0]), "r"(a[1]), "r"(a[2]), "r"(a[3]), "r"(b0), "r"(b1));
}

// ===========================================================================
// 1) Patchify + fp16 hi/lo split into A' = [Ah | Ah | Al].
// ===========================================================================
__global__ void patchify_split_kernel(const float* __restrict__ pixels) {
    int idx = blockIdx.x * blockDim.x + threadIdx.x;
    if (idx >= MROWS * PD) return;
    int d = idx % PD;
    int m = idx / PD;
    int p = m % NP, b = m / NP;
    int ch = d >> 6;
    int rem = d & 63;
    int pr = rem >> 3, pc = rem & 7;
    int r = p >> 3, c = p & 7;
    float v = pixels[(((size_t)b * 3 + ch) * 64 + (r * 8 + pr)) * 64 + (c * 8 + pc)];
    g_patches[(size_t)m * PD + d] = v;
    __half h = __float2half_rn(v);
    __half l = __float2half_rn(v - __half2float(h));
    __half* row = g_a + (size_t)m * KP;
    row[d] = h;
    row[PD + d] = h;
    row[2 * PD + d] = l;
}

// ===========================================================================
// 2) Codebook split into transposed B'^T = [Bh ; Bl ; Bh], n-contiguous.
// ===========================================================================
__global__ void split_codebook_kernel(const float* __restrict__ cb) {
    int idx = blockIdx.x * blockDim.x + threadIdx.x;
    if (idx >= KP * KC) return;
    int n = idx % KC;
    int r = idx / KC;
    int d = (r < PD) ? r : ((r < 2 * PD) ? r - PD : r - 2 * PD);
    float v = cb[(size_t)n * PD + d];
    __half h = __float2half_rn(v);
    __half o = (r >= PD && r < 2 * PD) ? __float2half_rn(v - __half2float(h)) : h;
    g_bT[idx] = o;
}

__global__ void zero_flag_kernel() { g_nflag = 0; }

// ===========================================================================
// 3) fp16 mma.sync GEMM + fused top-2 argmax.
//    512 blocks x 256 threads. A tile (128x576 fp16) resident in smem,
//    B streamed in 64x128 k-major chunks (double-buffered cp.async).
//    Warp tile 32(M) x 64(N): warps (wm = wid>>1, wn = wid&1).
// ===========================================================================
__global__ __launch_bounds__(256, 1) void gemm_mma_kernel(float* __restrict__ outI) {
    extern __shared__ char smem[];
    const uint32_t sA = smem_u32(smem);
    const uint32_t sB = sA + ASMEM;
    const int tid = threadIdx.x;
    const int wid = tid >> 5;
    const int lane = tid & 31;
    const int wm = wid >> 1;    // 0..3
    const int wn = wid & 1;     // 0..1
    const int m0 = blockIdx.x * BM;

    // ---- A tile -> smem (swizzled, once) ----
    {
        const __half* gA = g_a + (size_t)m0 * KP;
        for (int i = tid; i < BM * (KP / 8); i += 256) {   // 9216 granules
            int r = i / (KP / 8), g = i % (KP / 8);
            cp16(sA + r * AROWB + ((g ^ (r & 7)) * 16), gA + (size_t)r * KP + g * 8);
        }
        CP_COMMIT();
    }
    // ---- B chunk 0 ----
    {
        const __half* src = g_bT;   // k0=0, n0=0
        for (int i = tid; i < KCH * (BN / 8); i += 256) {  // 1024 granules
            int r = i >> 4, g = i & 15;
            cp16(sB + r * (BN * 2) + ((g ^ (r & 7)) * 16), src + (size_t)r * KC + g * 8);
        }
        CP_COMMIT();
    }

    float acc[2][4][2][4];
#pragma unroll
    for (int a = 0; a < 2; a++)
#pragma unroll
        for (int b = 0; b < 4; b++)
#pragma unroll
            for (int c = 0; c < 2; c++)
#pragma unroll
                for (int d = 0; d < 4; d++) acc[a][b][c][d] = 0.0f;

    float b1[4], b2[4];
    int   i1[4];
#pragma unroll
    for (int s = 0; s < 4; s++) { b1[s] = -3.0e38f; b2[s] = -3.0e38f; i1[s] = 0; }

    for (int it = 0; it < TOTIT; ++it) {
        const int kc = it % NCHUNK;
        // prefetch next chunk
        if (it + 1 < TOTIT) {
            int t2 = (it + 1) / NCHUNK, k2 = (it + 1) % NCHUNK;
            const __half* src = g_bT + (size_t)(k2 * KCH) * KC + t2 * BN;
            uint32_t dst = sB + ((it + 1) & 1) * BBUF;
            for (int i = tid; i < KCH * (BN / 8); i += 256) {
                int r = i >> 4, g = i & 15;
                cp16(dst + r * (BN * 2) + ((g ^ (r & 7)) * 16), src + (size_t)r * KC + g * 8);
            }
            CP_COMMIT();
            CP_WAIT(1);
        } else {
            CP_WAIT(0);
        }
        __syncthreads();

        // ---- compute chunk it ----
        const uint32_t bbuf = sB + (it & 1) * BBUF;
#pragma unroll
        for (int kk = 0; kk < 4; kk++) {
            uint32_t afr[2][4];
#pragma unroll
            for (int mm = 0; mm < 2; mm++) {
                int r = wm * 32 + mm * 16 + (lane & 15);
                int g = kc * 8 + kk * 2 + (lane >> 4);
                ldsm4(afr[mm], sA + r * AROWB + ((g ^ (r & 7)) * 16));
            }
#pragma unroll
            for (int nn2 = 0; nn2 < 4; nn2++) {
                int krow = kk * 16 + (lane & 7) + ((lane & 16) ? 8 : 0);
                int g = wn * 8 + nn2 * 2 + ((lane >> 3) & 1);
                uint32_t bfr[4];
                ldsm4t(bfr, bbuf + krow * (BN * 2) + ((g ^ (krow & 7)) * 16));
#pragma unroll
                for (int mm = 0; mm < 2; mm++) {
                    mma16816(acc[mm][nn2][0], afr[mm], bfr[0], bfr[2]);
                    mma16816(acc[mm][nn2][1], afr[mm], bfr[1], bfr[3]);
                }
            }
        }

        // ---- end of N-tile: fold accumulators into running top-2 ----
        if (kc == NCHUNK - 1) {
            const int colb = (it / NCHUNK) * BN + wn * 64 + 2 * (lane & 3);
#pragma unroll
            for (int s = 0; s < 4; s++) {
                const int mm = s >> 1, h = s & 1;
#pragma unroll
                for (int nn2 = 0; nn2 < 4; nn2++) {
#pragma unroll
                    for (int hn = 0; hn < 2; hn++) {
                        int cb = colb + nn2 * 16 + hn * 8;
                        float v0 = acc[mm][nn2][hn][h * 2];
                        if (v0 > b1[s]) { b2[s] = b1[s]; b1[s] = v0; i1[s] = cb; }
                        else if (v0 > b2[s]) b2[s] = v0;
                        float v1 = acc[mm][nn2][hn][h * 2 + 1];
                        if (v1 > b1[s]) { b2[s] = b1[s]; b1[s] = v1; i1[s] = cb + 1; }
                        else if (v1 > b2[s]) b2[s] = v1;
                        acc[mm][nn2][hn][h * 2] = 0.0f;
                        acc[mm][nn2][hn][h * 2 + 1] = 0.0f;
                    }
                }
            }
        }
        __syncthreads();
    }

    // ---- quad-lane merge (lanes sharing rows: same lane>>2) ----
#pragma unroll
    for (int s = 0; s < 4; s++) {
#pragma unroll
        for (int ofs = 1; ofs <= 2; ofs <<= 1) {
            float w1 = __shfl_xor_sync(0xFFFFFFFFu, b1[s], ofs);
            float w2 = __shfl_xor_sync(0xFFFFFFFFu, b2[s], ofs);
            int   k1 = __shfl_xor_sync(0xFFFFFFFFu, i1[s], ofs);
            if (w1 > b1[s] || (w1 == b1[s] && k1 < i1[s])) {
                b2[s] = fmaxf(b1[s], w2); b1[s] = w1; i1[s] = k1;
            } else {
                b2[s] = fmaxf(b2[s], w1);
            }
        }
    }

    // ---- cross-warp reduction through smem (reuse B region) ----
    float* rv1 = (float*)(smem + ASMEM);
    float* rv2 = rv1 + BM * 2;
    int*   ri1 = (int*)(rv2 + BM * 2);
    if ((lane & 3) == 0) {
#pragma unroll
        for (int s = 0; s < 4; s++) {
            int row = wm * 32 + (s >> 1) * 16 + (s & 1) * 8 + (lane >> 2);
            rv1[row * 2 + wn] = b1[s];
            rv2[row * 2 + wn] = b2[s];
            ri1[row * 2 + wn] = i1[s];
        }
    }
    __syncthreads();
    if (tid < BM) {
        float v1 = rv1[tid * 2], v2 = rv2[tid * 2];
        int   j1 = ri1[tid * 2];
        float w1 = rv1[tid * 2 + 1], w2 = rv2[tid * 2 + 1];
        int   k1 = ri1[tid * 2 + 1];
        if (w1 > v1 || (w1 == v1 && k1 < j1)) { v2 = fmaxf(v1, w2); v1 = w1; j1 = k1; }
        else v2 = fmaxf(v2, w1);
        int row = m0 + tid;
        g_indices[row] = j1;
        outI[row] = (float)j1;
        if (v1 - v2 < DELTA) {
            int s = atomicAdd(&g_nflag, 1);
            g_flagged[s] = row;
        }
    }
}

// ===========================================================================
// 4) Exact fp32 rescore for near-tie rows.
// ===========================================================================
__global__ __launch_bounds__(256) void rescore_kernel(const float* __restrict__ cb,
                                                      float* __restrict__ outI) {
    __shared__ float sp[PD];
    __shared__ float sv[256];
    __shared__ int si[256];
    const int nf = g_nflag;
    for (int f = blockIdx.x; f < nf; f += gridDim.x) {
        const int m = g_flagged[f];
        for (int d = threadIdx.x; d < PD; d += 256) sp[d] = g_patches[(size_t)m * PD + d];
        __syncthreads();
        float bv = -3.0e38f;
        int bi = 0;
        for (int k = threadIdx.x; k < KC; k += 256) {
            const float* crow = cb + (size_t)k * PD;
            float s = 0.0f;
#pragma unroll 8
            for (int d = 0; d < PD; d++) s = fmaf(sp[d], crow[d], s);
            if (s > bv) { bv = s; bi = k; }
        }
        sv[threadIdx.x] = bv;
        si[threadIdx.x] = bi;
        __syncthreads();
        if (threadIdx.x == 0) {
            float v = sv[0]; int ix = si[0];
            for (int t = 1; t < 256; t++)
                if (sv[t] > v || (sv[t] == v && si[t] < ix)) { v = sv[t]; ix = si[t]; }
            g_indices[m] = ix;
            outI[m] = (float)ix;
        }
        __syncthreads();
    }
}

// ===========================================================================
// 5) Embedding means (global + agent 3x3).
// ===========================================================================
__global__ __launch_bounds__(256) void embed_mean_kernel(
    const float* __restrict__ emb, float* __restrict__ outR, float* __restrict__ outL)
{
    const int b = blockIdx.x;
    __shared__ int sIdx[NP];
    if (threadIdx.x < NP) sIdx[threadIdx.x] = g_indices[b * NP + threadIdx.x];
    __syncthreads();
    for (int e = threadIdx.x; e < ED; e += 256) {
        float s = 0.0f, sl = 0.0f;
#pragma unroll 8
        for (int p = 0; p < NP; p++) {
            float v = emb[(size_t)sIdx[p] * ED + e];
            s += v;
            int r = p >> 3, c = p & 7;
            if (r >= 3 && r < 6 && c >= 3 && c < 6) sl += v;
        }
        outR[(size_t)b * ED + e] = s * (1.0f / 64.0f);
        outL[(size_t)b * ED + e] = sl * (1.0f / 9.0f);
    }
}

// ===========================================================================
// 6) VSA over 16 central patches.
// ===========================================================================
__global__ __launch_bounds__(256) void vsa_kernel(
    const float* __restrict__ cbv, const float* __restrict__ roles,
    float* __restrict__ outV)
{
    const int b = blockIdx.x;
    __shared__ int sIdx[16];
    __shared__ int sPos[16];
    if (threadIdx.x < 16) {
        int r = 2 + (threadIdx.x >> 2);
        int c = 2 + (threadIdx.x & 3);
        int p = r * 8 + c;
        sPos[threadIdx.x] = p;
        sIdx[threadIdx.x] = g_indices[b * NP + p];
    }
    __syncthreads();
    for (int v = threadIdx.x; v < VD; v += 256) {
        int cnt = 0;
#pragma unroll
        for (int t = 0; t < 16; t++) {
            float a = cbv[(size_t)sIdx[t] * VD + v];
            float q = roles[(size_t)sPos[t] * VD + v];
            cnt += (a != q);
        }
        outV[(size_t)b * VD + v] = (cnt > 8) ? 1.0f : 0.0f;
    }
}

// ===========================================================================
extern "C" void kernel_launch(void* const* d_in, const int* in_sizes, int n_in,
                              void* d_out, int out_size)
{
    const float* pixels     = (const float*)d_in[0];
    const float* codebook   = (const float*)d_in[1];
    const float* embeddings = (const float*)d_in[2];
    const float* cbv        = (const float*)d_in[3];
    const float* roles      = (const float*)d_in[4];

    float* out  = (float*)d_out;
    float* outR = out;
    float* outV = out + (size_t)BATCH * ED;
    float* outI = out + 2 * (size_t)BATCH * ED;
    float* outL = out + 2 * (size_t)BATCH * ED + (size_t)BATCH * NP;

    static bool attr_set = false;
    if (!attr_set) {
        cudaFuncSetAttribute(gemm_mma_kernel,
                             cudaFuncAttributeMaxDynamicSharedMemorySize, GEMM_SMEM);
        attr_set = true;
    }

    patchify_split_kernel<<<(MROWS * PD + 255) / 256, 256>>>(pixels);
    split_codebook_kernel<<<(KP * KC + 255) / 256, 256>>>(codebook);
    zero_flag_kernel<<<1, 1>>>();
    gemm_mma_kernel<<<MROWS / BM, 256, GEMM_SMEM>>>(outI);
    rescore_kernel<<<512, 256>>>(codebook, outI);
    embed_mean_kernel<<<BATCH, 256>>>(embeddings, outR, outL);
    vsa_kernel<<<BATCH, 256>>>(cbv, roles, outV);
}

// round 4
// speedup vs baseline: 2.2553x; 1.0342x over previous
#include <cuda_runtime.h>
#include <cuda_fp16.h>
#include <cstdint>

// ===========================================================================
// VQPatchEncoder — fp16-split mma.sync GEMM (sm_100 baseline ISA) +
// exact-argmax rescore path.
// sim = AhBh + AhBl + AlBh (fp16 hi/lo split, abs err ~1e-5); rows with
// top2 gap < DELTA rescored in exact fp32 -> bit-exact argmax.
// R4: 512 threads (16 warps, 32x32 warp tiles), 3-stage cp.async pipeline
// with a single __syncthreads per k-chunk.
// ===========================================================================

#define BATCH 1024
#define NP    64
#define PD    192
#define KC    4096
#define ED    2048
#define VD    2048
#define MROWS (BATCH * NP)      // 65536
#define KP    576                // split-K: [Ah|Ah|Al] x [Bh;Bl;Bh]
#define BM    128
#define BN    128
#define KCH   64                 // k per chunk
#define NCHUNK (KP / KCH)        // 9
#define NTILE  (KC / BN)         // 32
#define TOTIT  (NTILE * NCHUNK)  // 288
#define AROWB  (KP * 2)          // 1152 B per A smem row
#define ASMEM  (BM * AROWB)      // 147456
#define BBUF   (KCH * BN * 2)    // 16384 per buffer
#define NBUF   3
#define GEMM_SMEM (ASMEM + NBUF * BBUF)   // 196608
#define GEMM_THREADS 512
#define DELTA 2e-4f

// ---- device-global scratch ------------------------------------------------
__device__ __half g_a [(size_t)MROWS * KP];     // A' rows (75 MB)
__device__ __half g_bT[(size_t)KP * KC];        // B'^T [k][n] (4.7 MB)
__device__ float  g_patches[(size_t)MROWS * PD];
__device__ int    g_indices[MROWS];
__device__ int    g_flagged[MROWS];
__device__ int    g_nflag;

__device__ __forceinline__ uint32_t smem_u32(const void* p) {
    uint32_t a;
    asm("{ .reg .u64 t; cvta.to.shared.u64 t, %1; cvt.u32.u64 %0, t; }"
        : "=r"(a) : "l"(p));
    return a;
}
__device__ __forceinline__ void cp16(uint32_t dst, const void* src) {
    asm volatile("cp.async.cg.shared.global [%0], [%1], 16;"
                 :: "r"(dst), "l"(src) : "memory");
}
#define CP_COMMIT() asm volatile("cp.async.commit_group;" ::: "memory")
#define CP_WAIT(n)  asm volatile("cp.async.wait_group %0;" :: "n"(n) : "memory")

__device__ __forceinline__ void ldsm4(uint32_t* r, uint32_t addr) {
    asm volatile("ldmatrix.sync.aligned.m8n8.x4.shared.b16 {%0,%1,%2,%3}, [%4];"
                 : "=r"(r[0]), "=r"(r[1]), "=r"(r[2]), "=r"(r[3]) : "r"(addr));
}
__device__ __forceinline__ void ldsm4t(uint32_t* r, uint32_t addr) {
    asm volatile("ldmatrix.sync.aligned.m8n8.x4.trans.shared.b16 {%0,%1,%2,%3}, [%4];"
                 : "=r"(r[0]), "=r"(r[1]), "=r"(r[2]), "=r"(r[3]) : "r"(addr));
}
__device__ __forceinline__ void mma16816(float* c, const uint32_t* a,
                                         uint32_t b0, uint32_t b1) {
    asm volatile(
        "mma.sync.aligned.m16n8k16.row.col.f32.f16.f16.f32 "
        "{%0,%1,%2,%3}, {%4,%5,%6,%7}, {%8,%9}, {%0,%1,%2,%3};"
        : "+f"(c[0]), "+f"(c[1]), "+f"(c[2]), "+f"(c[3])
        : "r"(a[0]), "r"(a[1]), "r"(a[2]), "r"(a[3]), "r"(b0), "r"(b1));
}

// ===========================================================================
// 1) Patchify + fp16 hi/lo split into A' = [Ah | Ah | Al].
// ===========================================================================
__global__ void patchify_split_kernel(const float* __restrict__ pixels) {
    int idx = blockIdx.x * blockDim.x + threadIdx.x;
    if (idx >= MROWS * PD) return;
    int d = idx % PD;
    int m = idx / PD;
    int p = m % NP, b = m / NP;
    int ch = d >> 6;
    int rem = d & 63;
    int pr = rem >> 3, pc = rem & 7;
    int r = p >> 3, c = p & 7;
    float v = pixels[(((size_t)b * 3 + ch) * 64 + (r * 8 + pr)) * 64 + (c * 8 + pc)];
    g_patches[(size_t)m * PD + d] = v;
    __half h = __float2half_rn(v);
    __half l = __float2half_rn(v - __half2float(h));
    __half* row = g_a + (size_t)m * KP;
    row[d] = h;
    row[PD + d] = h;
    row[2 * PD + d] = l;
}

// ===========================================================================
// 2) Codebook split into transposed B'^T = [Bh ; Bl ; Bh], n-contiguous.
// ===========================================================================
__global__ void split_codebook_kernel(const float* __restrict__ cb) {
    int idx = blockIdx.x * blockDim.x + threadIdx.x;
    if (idx >= KP * KC) return;
    int n = idx % KC;
    int r = idx / KC;
    int d = (r < PD) ? r : ((r < 2 * PD) ? r - PD : r - 2 * PD);
    float v = cb[(size_t)n * PD + d];
    __half h = __float2half_rn(v);
    __half o = (r >= PD && r < 2 * PD) ? __float2half_rn(v - __half2float(h)) : h;
    g_bT[idx] = o;
}

__global__ void zero_flag_kernel() { g_nflag = 0; }

// ===========================================================================
// 3) fp16 mma.sync GEMM + fused top-2 argmax.
//    512 blocks x 512 threads; 16 warps in 4x4 grid, warp tile 32Mx32N.
//    A tile (128x576) resident in smem; B in 64x128 chunks, 3-buffer
//    cp.async pipeline, one __syncthreads per chunk.
// ===========================================================================
__global__ __launch_bounds__(GEMM_THREADS, 1) void gemm_mma_kernel(float* __restrict__ outI) {
    extern __shared__ char smem[];
    const uint32_t sA = smem_u32(smem);
    const uint32_t sB = sA + ASMEM;
    const int tid = threadIdx.x;
    const int wid = tid >> 5;
    const int lane = tid & 31;
    const int wm = wid >> 2;    // 0..3  (M strip of 32)
    const int wn = wid & 3;     // 0..3  (N strip of 32)
    const int m0 = blockIdx.x * BM;

    // ---- A tile -> smem (group 0) ----
    {
        const __half* gA = g_a + (size_t)m0 * KP;
        for (int i = tid; i < BM * (KP / 8); i += GEMM_THREADS) {   // 9216 granules
            int r = i / (KP / 8), g = i % (KP / 8);
            cp16(sA + r * AROWB + ((g ^ (r & 7)) * 16), gA + (size_t)r * KP + g * 8);
        }
        CP_COMMIT();
    }
    // ---- B chunks 0,1 (groups 1,2) ----
#pragma unroll
    for (int pre = 0; pre < 2; pre++) {
        const __half* src = g_bT + (size_t)(pre * KCH) * KC;   // tile 0
        uint32_t dst = sB + pre * BBUF;
        for (int i = tid; i < KCH * (BN / 8); i += GEMM_THREADS) {  // 1024 granules
            int r = i >> 4, g = i & 15;
            cp16(dst + r * (BN * 2) + ((g ^ (r & 7)) * 16), src + (size_t)r * KC + g * 8);
        }
        CP_COMMIT();
    }

    float acc[2][2][2][4];
#pragma unroll
    for (int a = 0; a < 2; a++)
#pragma unroll
        for (int b = 0; b < 2; b++)
#pragma unroll
            for (int c = 0; c < 2; c++)
#pragma unroll
                for (int d = 0; d < 4; d++) acc[a][b][c][d] = 0.0f;

    float b1[4], b2[4];
    int   i1[4];
#pragma unroll
    for (int s = 0; s < 4; s++) { b1[s] = -3.0e38f; b2[s] = -3.0e38f; i1[s] = 0; }

    for (int it = 0; it < TOTIT; ++it) {
        const int kc = it % NCHUNK;
        CP_WAIT(1);
        __syncthreads();

        // ---- compute chunk it from buf[it % 3] ----
        const uint32_t bbuf = sB + (it % NBUF) * BBUF;
#pragma unroll
        for (int kk = 0; kk < 4; kk++) {
            uint32_t afr[2][4];
#pragma unroll
            for (int mm = 0; mm < 2; mm++) {
                int r = wm * 32 + mm * 16 + (lane & 15);
                int g = kc * 8 + kk * 2 + (lane >> 4);
                ldsm4(afr[mm], sA + r * AROWB + ((g ^ (r & 7)) * 16));
            }
#pragma unroll
            for (int nn2 = 0; nn2 < 2; nn2++) {
                int krow = kk * 16 + (lane & 7) + ((lane & 16) ? 8 : 0);
                int g = wn * 4 + nn2 * 2 + ((lane >> 3) & 1);
                uint32_t bfr[4];
                ldsm4t(bfr, bbuf + krow * (BN * 2) + ((g ^ (krow & 7)) * 16));
#pragma unroll
                for (int mm = 0; mm < 2; mm++) {
                    mma16816(acc[mm][nn2][0], afr[mm], bfr[0], bfr[2]);
                    mma16816(acc[mm][nn2][1], afr[mm], bfr[1], bfr[3]);
                }
            }
        }

        // ---- end of N-tile: fold accumulators into running top-2 ----
        if (kc == NCHUNK - 1) {
            const int colb = (it / NCHUNK) * BN + wn * 32 + 2 * (lane & 3);
#pragma unroll
            for (int s = 0; s < 4; s++) {
                const int mm = s >> 1, h = s & 1;
#pragma unroll
                for (int nn2 = 0; nn2 < 2; nn2++) {
#pragma unroll
                    for (int hn = 0; hn < 2; hn++) {
                        int cb = colb + nn2 * 16 + hn * 8;
                        float v0 = acc[mm][nn2][hn][h * 2];
                        if (v0 > b1[s]) { b2[s] = b1[s]; b1[s] = v0; i1[s] = cb; }
                        else if (v0 > b2[s]) b2[s] = v0;
                        float v1 = acc[mm][nn2][hn][h * 2 + 1];
                        if (v1 > b1[s]) { b2[s] = b1[s]; b1[s] = v1; i1[s] = cb + 1; }
                        else if (v1 > b2[s]) b2[s] = v1;
                        acc[mm][nn2][hn][h * 2] = 0.0f;
                        acc[mm][nn2][hn][h * 2 + 1] = 0.0f;
                    }
                }
            }
        }

        // ---- prefetch chunk it+2 into buf[(it+2)%3] (freed by the barrier) ----
        if (it + 2 < TOTIT) {
            int t2 = (it + 2) / NCHUNK, k2 = (it + 2) % NCHUNK;
            const __half* src = g_bT + (size_t)(k2 * KCH) * KC + t2 * BN;
            uint32_t dst = sB + ((it + 2) % NBUF) * BBUF;
            for (int i = tid; i < KCH * (BN / 8); i += GEMM_THREADS) {
                int r = i >> 4, g = i & 15;
                cp16(dst + r * (BN * 2) + ((g ^ (r & 7)) * 16), src + (size_t)r * KC + g * 8);
            }
            CP_COMMIT();
        }
    }

    // ---- quad-lane merge (lanes sharing rows) ----
#pragma unroll
    for (int s = 0; s < 4; s++) {
#pragma unroll
        for (int ofs = 1; ofs <= 2; ofs <<= 1) {
            float w1 = __shfl_xor_sync(0xFFFFFFFFu, b1[s], ofs);
            float w2 = __shfl_xor_sync(0xFFFFFFFFu, b2[s], ofs);
            int   k1 = __shfl_xor_sync(0xFFFFFFFFu, i1[s], ofs);
            if (w1 > b1[s] || (w1 == b1[s] && k1 < i1[s])) {
                b2[s] = fmaxf(b1[s], w2); b1[s] = w1; i1[s] = k1;
            } else {
                b2[s] = fmaxf(b2[s], w1);
            }
        }
    }

    // ---- cross-warp reduction via smem (reuse B buffers) ----
    __syncthreads();
    float* rv1 = (float*)(smem + ASMEM);
    float* rv2 = rv1 + BM * 4;
    int*   ri1 = (int*)(rv2 + BM * 4);
    if ((lane & 3) == 0) {
#pragma unroll
        for (int s = 0; s < 4; s++) {
            int row = wm * 32 + (s >> 1) * 16 + (s & 1) * 8 + (lane >> 2);
            rv1[row * 4 + wn] = b1[s];
            rv2[row * 4 + wn] = b2[s];
            ri1[row * 4 + wn] = i1[s];
        }
    }
    __syncthreads();
    if (tid < BM) {
        float v1 = rv1[tid * 4], v2 = rv2[tid * 4];
        int   j1 = ri1[tid * 4];
#pragma unroll
        for (int t = 1; t < 4; t++) {
            float w1 = rv1[tid * 4 + t], w2 = rv2[tid * 4 + t];
            int   k1 = ri1[tid * 4 + t];
            if (w1 > v1 || (w1 == v1 && k1 < j1)) { v2 = fmaxf(v1, w2); v1 = w1; j1 = k1; }
            else v2 = fmaxf(v2, w1);
        }
        int row = m0 + tid;
        g_indices[row] = j1;
        outI[row] = (float)j1;
        if (v1 - v2 < DELTA) {
            int s = atomicAdd(&g_nflag, 1);
            g_flagged[s] = row;
        }
    }
}

// ===========================================================================
// 4) Exact fp32 rescore for near-tie rows.
// ===========================================================================
__global__ __launch_bounds__(256) void rescore_kernel(const float* __restrict__ cb,
                                                      float* __restrict__ outI) {
    __shared__ float sp[PD];
    __shared__ float sv[256];
    __shared__ int si[256];
    const int nf = g_nflag;
    for (int f = blockIdx.x; f < nf; f += gridDim.x) {
        const int m = g_flagged[f];
        for (int d = threadIdx.x; d < PD; d += 256) sp[d] = g_patches[(size_t)m * PD + d];
        __syncthreads();
        float bv = -3.0e38f;
        int bi = 0;
        for (int k = threadIdx.x; k < KC; k += 256) {
            const float* crow = cb + (size_t)k * PD;
            float s = 0.0f;
#pragma unroll 8
            for (int d = 0; d < PD; d++) s = fmaf(sp[d], crow[d], s);
            if (s > bv) { bv = s; bi = k; }
        }
        sv[threadIdx.x] = bv;
        si[threadIdx.x] = bi;
        __syncthreads();
        if (threadIdx.x == 0) {
            float v = sv[0]; int ix = si[0];
            for (int t = 1; t < 256; t++)
                if (sv[t] > v || (sv[t] == v && si[t] < ix)) { v = sv[t]; ix = si[t]; }
            g_indices[m] = ix;
            outI[m] = (float)ix;
        }
        __syncthreads();
    }
}

// ===========================================================================
// 5) Embedding means (global + agent 3x3). 2 blocks per image.
// ===========================================================================
__global__ __launch_bounds__(256) void embed_mean_kernel(
    const float* __restrict__ emb, float* __restrict__ outR, float* __restrict__ outL)
{
    const int b = blockIdx.x;
    const int e0 = blockIdx.y * (ED / 2);
    __shared__ int sIdx[NP];
    if (threadIdx.x < NP) sIdx[threadIdx.x] = g_indices[b * NP + threadIdx.x];
    __syncthreads();
    for (int e = e0 + threadIdx.x; e < e0 + ED / 2; e += 256) {
        float s = 0.0f, sl = 0.0f;
#pragma unroll 8
        for (int p = 0; p < NP; p++) {
            float v = emb[(size_t)sIdx[p] * ED + e];
            s += v;
            int r = p >> 3, c = p & 7;
            if (r >= 3 && r < 6 && c >= 3 && c < 6) sl += v;
        }
        outR[(size_t)b * ED + e] = s * (1.0f / 64.0f);
        outL[(size_t)b * ED + e] = sl * (1.0f / 9.0f);
    }
}

// ===========================================================================
// 6) VSA over 16 central patches. 2 blocks per image.
// ===========================================================================
__global__ __launch_bounds__(256) void vsa_kernel(
    const float* __restrict__ cbv, const float* __restrict__ roles,
    float* __restrict__ outV)
{
    const int b = blockIdx.x;
    const int v0 = blockIdx.y * (VD / 2);
    __shared__ int sIdx[16];
    __shared__ int sPos[16];
    if (threadIdx.x < 16) {
        int r = 2 + (threadIdx.x >> 2);
        int c = 2 + (threadIdx.x & 3);
        int p = r * 8 + c;
        sPos[threadIdx.x] = p;
        sIdx[threadIdx.x] = g_indices[b * NP + p];
    }
    __syncthreads();
    for (int v = v0 + threadIdx.x; v < v0 + VD / 2; v += 256) {
        int cnt = 0;
#pragma unroll
        for (int t = 0; t < 16; t++) {
            float a = cbv[(size_t)sIdx[t] * VD + v];
            float q = roles[(size_t)sPos[t] * VD + v];
            cnt += (a != q);
        }
        outV[(size_t)b * VD + v] = (cnt > 8) ? 1.0f : 0.0f;
    }
}

// ===========================================================================
extern "C" void kernel_launch(void* const* d_in, const int* in_sizes, int n_in,
                              void* d_out, int out_size)
{
    const float* pixels     = (const float*)d_in[0];
    const float* codebook   = (const float*)d_in[1];
    const float* embeddings = (const float*)d_in[2];
    const float* cbv        = (const float*)d_in[3];
    const float* roles      = (const float*)d_in[4];

    float* out  = (float*)d_out;
    float* outR = out;
    float* outV = out + (size_t)BATCH * ED;
    float* outI = out + 2 * (size_t)BATCH * ED;
    float* outL = out + 2 * (size_t)BATCH * ED + (size_t)BATCH * NP;

    static bool attr_set = false;
    if (!attr_set) {
        cudaFuncSetAttribute(gemm_mma_kernel,
                             cudaFuncAttributeMaxDynamicSharedMemorySize, GEMM_SMEM);
        attr_set = true;
    }

    patchify_split_kernel<<<(MROWS * PD + 255) / 256, 256>>>(pixels);
    split_codebook_kernel<<<(KP * KC + 255) / 256, 256>>>(codebook);
    zero_flag_kernel<<<1, 1>>>();
    gemm_mma_kernel<<<MROWS / BM, GEMM_THREADS, GEMM_SMEM>>>(outI);
    rescore_kernel<<<512, 256>>>(codebook, outI);
    embed_mean_kernel<<<dim3(BATCH, 2), 256>>>(embeddings, outR, outL);
    vsa_kernel<<<dim3(BATCH, 2), 256>>>(cbv, roles, outV);
}